// round 9
// baseline (speedup 1.0000x reference)
#include <cuda_runtime.h>
#include <cuda_fp16.h>
#include <cstdint>

#define H_IN 56
#define W_IN 56
#define C_IN 128
#define KOUT 256
#define NIMG 32
#define W2   28                      // output-pair columns
#define P2TOT (NIMG*H_IN*W2)         // 50176 GEMM rows
#define P2IMG (H_IN*W2)              // 1568
#define VSTRIDE ((size_t)P2TOT*C_IN) // per-t V plane
#define NCHUNK 24                    // 4 GEMMs x 3 r x 2 c-halves, K=64 each

// Winograd-transformed scratch
__device__ __align__(128) __half g_v[4 * VSTRIDE];            // [t][p2][c]
__device__ __align__(128) __half g_u[4 * 3 * KOUT * C_IN];    // [t][r][k][c]

__constant__ int c_ord[4] = {1, 2, 0, 3};   // GEMM processing order -> t

__device__ __forceinline__ float quant16f(float v) {
    float r = rintf(v * 4096.0f);
    r = fminf(fmaxf(r, -32768.0f), 32767.0f);
    return r * (1.0f / 4096.0f);
}

__device__ __forceinline__ uint32_t su32(const void* p) {
    uint32_t a;
    asm("{ .reg .u64 t; cvta.to.shared.u64 t, %1; cvt.u32.u64 %0, t; }"
        : "=r"(a) : "l"(p));
    return a;
}

// ---------------- pre-kernels ----------------
// V transform: one (n,h) row, all 128 c. d_s = qx[w=2*w2-1+s] (zero-padded).
__global__ void prep_xw(const float* __restrict__ x) {
    __shared__ __half xs[C_IN][58];   // [c][w+1], w=-1..56
    const int h = blockIdx.x;
    const int n = blockIdx.y;
    const int tid = threadIdx.x;

    for (int i = tid; i < C_IN * W_IN; i += 256) {
        int c = i / W_IN, w = i - c * W_IN;
        xs[c][w + 1] = __float2half(
            quant16f(x[(((size_t)n * C_IN + c) * H_IN + h) * W_IN + w]));
    }
    if (tid < C_IN) { xs[tid][0] = __float2half(0.f); xs[tid][57] = __float2half(0.f); }
    __syncthreads();

    const size_t pbase = ((size_t)(n * H_IN + h) * W2) * C_IN;
    for (int j = tid; j < W2 * (C_IN / 2); j += 256) {
        int cp = (j & 63) * 2, w2 = j >> 6;
        float d0a = __half2float(xs[cp][2 * w2]);
        float d1a = __half2float(xs[cp][2 * w2 + 1]);
        float d2a = __half2float(xs[cp][2 * w2 + 2]);
        float d3a = __half2float(xs[cp][2 * w2 + 3]);
        float d0b = __half2float(xs[cp + 1][2 * w2]);
        float d1b = __half2float(xs[cp + 1][2 * w2 + 1]);
        float d2b = __half2float(xs[cp + 1][2 * w2 + 2]);
        float d3b = __half2float(xs[cp + 1][2 * w2 + 3]);
        size_t o = pbase + (size_t)w2 * C_IN + cp;
        *(__half2*)&g_v[o]               = __floats2half2_rn(d0a - d2a, d0b - d2b);
        *(__half2*)&g_v[VSTRIDE + o]     = __floats2half2_rn(d1a + d2a, d1b + d2b);
        *(__half2*)&g_v[2 * VSTRIDE + o] = __floats2half2_rn(d2a - d1a, d2b - d1b);
        *(__half2*)&g_v[3 * VSTRIDE + o] = __floats2half2_rn(d1a - d3a, d1b - d3b);
    }
}

// U transform: [t][r][k][c]; t=3 negated so y1 accumulates -m3 directly.
__global__ void prep_wu(const float* __restrict__ w) {
    int idx = blockIdx.x * 256 + threadIdx.x;
    if (idx >= 4 * 3 * KOUT * C_IN) return;
    int t = idx / (3 * KOUT * C_IN);
    int r = (idx / (KOUT * C_IN)) % 3;
    int k = (idx >> 7) & 255;
    int c = idx & 127;
    const float* gp = w + (size_t)k * 1152 + c * 9 + r * 3;
    float g0 = quant16f(gp[0]), g1 = quant16f(gp[1]), g2 = quant16f(gp[2]);
    float u;
    if (t == 0) u = g0;
    else if (t == 1) u = 0.5f * (g0 + g1 + g2);
    else if (t == 2) u = 0.5f * (g0 - g1 + g2);
    else u = -g2;
    g_u[((size_t)((t * 3 + r) * KOUT + k)) * C_IN + c] = __float2half(u);
}

// ---------------- main kernel: 128x64 CTA, 4 warps, 2 CTAs/SM ----------------
// smem: 4 stages x (A 16KB [128 p2 x 128B] + B 8KB [64 k x 128B])
#define A_ST(s) ((s) * 16384u)
#define B_ST(s) (65536u + (s) * 8192u)
#define SMEM_TOTAL 98304

__device__ __forceinline__ void cp16(uint32_t dst, const void* src, uint32_t ssz) {
    asm volatile("cp.async.cg.shared.global [%0], [%1], 16, %2;"
                 :: "r"(dst), "l"(src), "r"(ssz) : "memory");
}

__device__ __forceinline__ void ldsm4(uint32_t* r, uint32_t addr) {
    asm volatile("ldmatrix.sync.aligned.m8n8.x4.shared.b16 {%0,%1,%2,%3}, [%4];"
                 : "=r"(r[0]), "=r"(r[1]), "=r"(r[2]), "=r"(r[3]) : "r"(addr));
}

__device__ __forceinline__ void mma16816(float* c, const uint32_t* a,
                                         uint32_t b0, uint32_t b1) {
    asm volatile(
        "mma.sync.aligned.m16n8k16.row.col.f32.f16.f16.f32 "
        "{%0,%1,%2,%3}, {%4,%5,%6,%7}, {%8,%9}, {%0,%1,%2,%3};"
        : "+f"(c[0]), "+f"(c[1]), "+f"(c[2]), "+f"(c[3])
        : "r"(a[0]), "r"(a[1]), "r"(a[2]), "r"(a[3]), "r"(b0), "r"(b1));
}

__global__ __launch_bounds__(128, 2) void conv_wino(float* __restrict__ out) {
    extern __shared__ char smem[];
    const uint32_t sb = su32(smem);
    const int tid = threadIdx.x;
    const int wid = tid >> 5, lane = tid & 31;
    const int wm = wid & 1, wn = wid >> 1;       // warp tile: 64m x 32n
    const unsigned p0 = blockIdx.x << 7;
    const int n0 = blockIdx.y << 6;

    // A staging: row = tid (128 rows x 128B), 8 cp16 per thread
    const unsigned p2 = p0 + tid;
    const unsigned nImg = p2 / P2IMG;
    const unsigned rem = p2 - nImg * P2IMG;
    const int ho = (int)(rem / W2);
    // B staging: row = tid&63 (64 rows x 128B), half = tid>>6 (4 cp16)
    const int rowB = tid & 63, halfB = tid >> 6;

    auto issue = [&](int kc) {
        const int st = kc & 3;
        const int gg = kc / 6;
        const int sub = kc - 6 * gg;
        const int r = sub >> 1;
        const int ch0 = (sub & 1) << 6;
        const int tsel = c_ord[gg];
        // A: V_t at input row hi = ho + r - 1 (zero-fill OOB)
        const int hi = ho + r - 1;
        const bool valid = (unsigned)hi < H_IN;
        const size_t arow = valid ? (size_t)p2 + (size_t)(r - 1) * W2 : (size_t)p2;
        const uint32_t ssz = valid ? 16u : 0u;
        const __half* asrc = g_v + (size_t)tsel * VSTRIDE + arow * C_IN + ch0;
        #pragma unroll
        for (int g = 0; g < 8; g++) {
            const uint32_t sw = (g ^ (tid & 7)) << 4;
            cp16(sb + A_ST(st) + tid * 128 + sw, asrc + g * 8, ssz);
        }
        // B: U_t[r][n0+rowB][ch0..]
        const __half* bsrc = g_u + ((size_t)((tsel * 3 + r) * KOUT + n0 + rowB)) * C_IN
                             + ch0;
        #pragma unroll
        for (int jj = 0; jj < 4; jj++) {
            const uint32_t g = halfB * 4 + jj;
            const uint32_t sw = (g ^ (rowB & 7)) << 4;
            cp16(sb + B_ST(st) + rowB * 128 + sw, bsrc + g * 8, 16u);
        }
        asm volatile("cp.async.commit_group;" ::: "memory");
    };

    float y0[4][4][4], y1[4][4][4];
    #pragma unroll
    for (int a = 0; a < 4; a++)
        #pragma unroll
        for (int b = 0; b < 4; b++)
            #pragma unroll
            for (int c = 0; c < 4; c++) { y0[a][b][c] = 0.f; y1[a][b][c] = 0.f; }

    auto run6 = [&](int gbase, float (&acc)[4][4][4]) {
        for (int sub = 0; sub < 6; sub++) {
            const int kc = gbase * 6 + sub;
            asm volatile("cp.async.wait_group 2;" ::: "memory");
            __syncthreads();
            if (kc + 3 < NCHUNK) issue(kc + 3);
            else asm volatile("cp.async.commit_group;" ::: "memory");

            const uint32_t Ab = sb + A_ST(kc & 3);
            const uint32_t Bb = sb + B_ST(kc & 3);
            #pragma unroll
            for (int stp = 0; stp < 4; stp++) {
                uint32_t ar[4][4], br[2][4];
                #pragma unroll
                for (int mt = 0; mt < 4; mt++) {
                    const int row = wm * 64 + mt * 16 + (lane & 7) + ((lane >> 3) & 1) * 8;
                    const int grp = 2 * stp + (lane >> 4);
                    ldsm4(ar[mt], Ab + row * 128 + ((grp ^ (row & 7)) << 4));
                }
                #pragma unroll
                for (int bt = 0; bt < 2; bt++) {
                    const int row = wn * 32 + bt * 16 + (lane & 7) + (lane >> 4) * 8;
                    const int grp = 2 * stp + ((lane >> 3) & 1);
                    ldsm4(br[bt], Bb + row * 128 + ((grp ^ (row & 7)) << 4));
                }
                #pragma unroll
                for (int mt = 0; mt < 4; mt++)
                    #pragma unroll
                    for (int nt = 0; nt < 4; nt++)
                        mma16816(acc[mt][nt], ar[mt],
                                 br[nt >> 1][(nt & 1) * 2], br[nt >> 1][(nt & 1) * 2 + 1]);
            }
            __syncthreads();
        }
    };

    issue(0); issue(1); issue(2);

    run6(0, y0);                    // t=1: y0 = m1
    #pragma unroll
    for (int a = 0; a < 4; a++)
        #pragma unroll
        for (int b = 0; b < 4; b++)
            #pragma unroll
            for (int c = 0; c < 4; c++) y1[a][b][c] = y0[a][b][c];   // y1 = m1
    run6(1, y0);                    // t=2: y0 = m1 + m2
    #pragma unroll
    for (int a = 0; a < 4; a++)
        #pragma unroll
        for (int b = 0; b < 4; b++)
            #pragma unroll
            for (int c = 0; c < 4; c++)
                y1[a][b][c] = 2.0f * y1[a][b][c] - y0[a][b][c];      // y1 = m1 - m2
    run6(2, y0);                    // t=0: y0 = m0 + m1 + m2
    run6(3, y1);                    // t=3 (negated U): y1 = m1 - m2 - m3

    asm volatile("cp.async.wait_group 0;" ::: "memory");
    __syncthreads();

    // ---- epilogue: (y0,y1) -> smem float2 [64 k][130] -> coalesced pairs ----
    float2* eb2 = (float2*)smem;
    {
        const int rr = lane >> 2, cc = (lane & 3) * 2;
        #pragma unroll
        for (int mt = 0; mt < 4; mt++)
            #pragma unroll
            for (int nt = 0; nt < 4; nt++) {
                const int m = wm * 64 + mt * 16 + rr;
                const int n = wn * 32 + nt * 8 + cc;
                eb2[n * 130 + m]           = make_float2(y0[mt][nt][0], y1[mt][nt][0]);
                eb2[(n + 1) * 130 + m]     = make_float2(y0[mt][nt][1], y1[mt][nt][1]);
                eb2[n * 130 + m + 8]       = make_float2(y0[mt][nt][2], y1[mt][nt][2]);
                eb2[(n + 1) * 130 + m + 8] = make_float2(y0[mt][nt][3], y1[mt][nt][3]);
            }
    }
    __syncthreads();
    for (int j = tid; j < 64 * 128; j += 128) {
        const int k = j >> 7;
        const int m = j & 127;
        const unsigned pp = p0 + m;
        const unsigned ni = pp / P2IMG;
        const unsigned rr = pp - ni * P2IMG;
        const unsigned hh = rr / W2;
        const unsigned w2 = rr - hh * W2;
        *(float2*)(out + ((size_t)(ni * KOUT + n0 + k) * H_IN + hh) * W_IN + 2 * w2)
            = eb2[k * 130 + m];
    }
}

extern "C" void kernel_launch(void* const* d_in, const int* in_sizes, int n_in,
                              void* d_out, int out_size) {
    const float* x = (const float*)d_in[0];
    const float* w = (const float*)d_in[1];
    float* out = (float*)d_out;

    cudaFuncSetAttribute(conv_wino, cudaFuncAttributeMaxDynamicSharedMemorySize,
                         SMEM_TOTAL);

    dim3 gx(H_IN, NIMG);
    prep_xw<<<gx, 256>>>(x);
    prep_wu<<<(4 * 3 * KOUT * C_IN + 255) / 256, 256>>>(w);
    dim3 grid(P2TOT / 128, KOUT / 64);
    conv_wino<<<grid, 128, SMEM_TOTAL>>>(out);
}

// round 10
// speedup vs baseline: 1.0646x; 1.0646x over previous
#include <cuda_runtime.h>
#include <cuda_fp16.h>
#include <cstdint>

#define H_IN 56
#define W_IN 56
#define C_IN 128
#define KOUT 256
#define NIMG 32
#define W2   28                      // output-pair columns
#define P2TOT (NIMG*H_IN*W2)         // 50176 GEMM rows
#define P2IMG (H_IN*W2)              // 1568
#define VSTRIDE ((size_t)P2TOT*C_IN) // per-t V plane
#define NCHUNK 12                    // 4 GEMMs x 3 r, K=128 each

// Winograd-transformed scratch
__device__ __align__(128) __half g_v[4 * VSTRIDE];            // [t][p2][c]
__device__ __align__(128) __half g_u[4 * 3 * KOUT * C_IN];    // [t][r][k][c]

__constant__ int c_ord[4] = {1, 2, 0, 3};   // GEMM processing order -> t

__device__ __forceinline__ float quant16f(float v) {
    float r = rintf(v * 4096.0f);
    r = fminf(fmaxf(r, -32768.0f), 32767.0f);
    return r * (1.0f / 4096.0f);
}

__device__ __forceinline__ uint32_t su32(const void* p) {
    uint32_t a;
    asm("{ .reg .u64 t; cvta.to.shared.u64 t, %1; cvt.u32.u64 %0, t; }"
        : "=r"(a) : "l"(p));
    return a;
}

// ---------------- pre-kernels ----------------
// V transform: one (n,h) row, all 128 c. d_s = qx[w=2*w2-1+s] (zero-padded).
__global__ void prep_xw(const float* __restrict__ x) {
    __shared__ __half xs[C_IN][58];   // [c][w+1], w=-1..56
    const int h = blockIdx.x;
    const int n = blockIdx.y;
    const int tid = threadIdx.x;

    for (int i = tid; i < C_IN * W_IN; i += 256) {
        int c = i / W_IN, w = i - c * W_IN;
        xs[c][w + 1] = __float2half(
            quant16f(x[(((size_t)n * C_IN + c) * H_IN + h) * W_IN + w]));
    }
    if (tid < C_IN) { xs[tid][0] = __float2half(0.f); xs[tid][57] = __float2half(0.f); }
    __syncthreads();

    const size_t pbase = ((size_t)(n * H_IN + h) * W2) * C_IN;
    for (int j = tid; j < W2 * (C_IN / 2); j += 256) {
        int cp = (j & 63) * 2, w2 = j >> 6;
        float d0a = __half2float(xs[cp][2 * w2]);
        float d1a = __half2float(xs[cp][2 * w2 + 1]);
        float d2a = __half2float(xs[cp][2 * w2 + 2]);
        float d3a = __half2float(xs[cp][2 * w2 + 3]);
        float d0b = __half2float(xs[cp + 1][2 * w2]);
        float d1b = __half2float(xs[cp + 1][2 * w2 + 1]);
        float d2b = __half2float(xs[cp + 1][2 * w2 + 2]);
        float d3b = __half2float(xs[cp + 1][2 * w2 + 3]);
        size_t o = pbase + (size_t)w2 * C_IN + cp;
        *(__half2*)&g_v[o]               = __floats2half2_rn(d0a - d2a, d0b - d2b);
        *(__half2*)&g_v[VSTRIDE + o]     = __floats2half2_rn(d1a + d2a, d1b + d2b);
        *(__half2*)&g_v[2 * VSTRIDE + o] = __floats2half2_rn(d2a - d1a, d2b - d1b);
        *(__half2*)&g_v[3 * VSTRIDE + o] = __floats2half2_rn(d1a - d3a, d1b - d3b);
    }
}

// U transform: [t][r][k][c]; t=3 negated so y1 accumulates -m3 directly.
__global__ void prep_wu(const float* __restrict__ w) {
    int idx = blockIdx.x * 256 + threadIdx.x;
    if (idx >= 4 * 3 * KOUT * C_IN) return;
    int t = idx / (3 * KOUT * C_IN);
    int r = (idx / (KOUT * C_IN)) % 3;
    int k = (idx >> 7) & 255;
    int c = idx & 127;
    const float* gp = w + (size_t)k * 1152 + c * 9 + r * 3;
    float g0 = quant16f(gp[0]), g1 = quant16f(gp[1]), g2 = quant16f(gp[2]);
    float u;
    if (t == 0) u = g0;
    else if (t == 1) u = 0.5f * (g0 + g1 + g2);
    else if (t == 2) u = 0.5f * (g0 - g1 + g2);
    else u = -g2;
    g_u[((size_t)((t * 3 + r) * KOUT + k)) * C_IN + c] = __float2half(u);
}

// ---------------- main kernel: 128x128 CTA, K=128 stacked chunks ----------------
// smem: 3 stages x (A 32KB + B 32KB). Each tile: 256 rows x 128B,
// rows 0-127 = ch 0-63, rows 128-255 = ch 64-127. Same per-row swizzle as R8.
#define A_ST(s) ((s) * 65536u)
#define B_ST(s) ((s) * 65536u + 32768u)
#define SMEM_TOTAL 196608

__device__ __forceinline__ void cp16(uint32_t dst, const void* src, uint32_t ssz) {
    asm volatile("cp.async.cg.shared.global [%0], [%1], 16, %2;"
                 :: "r"(dst), "l"(src), "r"(ssz) : "memory");
}

__device__ __forceinline__ void ldsm4(uint32_t* r, uint32_t addr) {
    asm volatile("ldmatrix.sync.aligned.m8n8.x4.shared.b16 {%0,%1,%2,%3}, [%4];"
                 : "=r"(r[0]), "=r"(r[1]), "=r"(r[2]), "=r"(r[3]) : "r"(addr));
}

__device__ __forceinline__ void mma16816(float* c, const uint32_t* a,
                                         uint32_t b0, uint32_t b1) {
    asm volatile(
        "mma.sync.aligned.m16n8k16.row.col.f32.f16.f16.f32 "
        "{%0,%1,%2,%3}, {%4,%5,%6,%7}, {%8,%9}, {%0,%1,%2,%3};"
        : "+f"(c[0]), "+f"(c[1]), "+f"(c[2]), "+f"(c[3])
        : "r"(a[0]), "r"(a[1]), "r"(a[2]), "r"(a[3]), "r"(b0), "r"(b1));
}

__global__ __launch_bounds__(256, 1) void conv_wino(float* __restrict__ out) {
    extern __shared__ char smem[];
    const uint32_t sb = su32(smem);
    const int tid = threadIdx.x;
    const int wid = tid >> 5, lane = tid & 31;
    const int wm = wid & 1, wn = wid >> 1;       // warp tile: 64m x 32n
    const unsigned p0 = blockIdx.x << 7;
    const int n0 = blockIdx.y << 7;

    // staging: thread tid owns stage row tid (128B, 8 cp16).
    // A row tid: pixel (tid&127), ch-half (tid>>7). B row tid: k (tid&127), ch-half.
    const int prow = tid & 127, chh = tid >> 7;
    const unsigned p2 = p0 + prow;
    const unsigned nImg = p2 / P2IMG;
    const unsigned rem = p2 - nImg * P2IMG;
    const int ho = (int)(rem / W2);

    auto issue = [&](int kc) {
        const int st = kc % 3;
        const int gg = kc / 3;
        const int r = kc - 3 * gg;
        const int tsel = c_ord[gg];
        // A: V_t at input row hi = ho + r - 1 (zero-fill OOB)
        const int hi = ho + r - 1;
        const bool valid = (unsigned)hi < H_IN;
        const size_t arow = valid ? (size_t)p2 + (size_t)(r - 1) * W2 : (size_t)p2;
        const uint32_t ssz = valid ? 16u : 0u;
        const __half* asrc = g_v + (size_t)tsel * VSTRIDE + arow * C_IN + chh * 64;
        // B: U_t[r][n0 + (tid&127)][chh*64 ..]
        const __half* bsrc = g_u + ((size_t)((tsel * 3 + r) * KOUT + n0 + prow)) * C_IN
                             + chh * 64;
        #pragma unroll
        for (int g = 0; g < 8; g++) {
            const uint32_t sw = (g ^ (tid & 7)) << 4;
            cp16(sb + A_ST(st) + tid * 128 + sw, asrc + g * 8, ssz);
            cp16(sb + B_ST(st) + tid * 128 + sw, bsrc + g * 8, 16u);
        }
        asm volatile("cp.async.commit_group;" ::: "memory");
    };

    float y0[4][4][4], y1[4][4][4];
    #pragma unroll
    for (int a = 0; a < 4; a++)
        #pragma unroll
        for (int b = 0; b < 4; b++)
            #pragma unroll
            for (int c = 0; c < 4; c++) { y0[a][b][c] = 0.f; y1[a][b][c] = 0.f; }

    auto run3 = [&](int gbase, float (&acc)[4][4][4]) {
        for (int sub = 0; sub < 3; sub++) {
            const int kc = gbase * 3 + sub;
            asm volatile("cp.async.wait_group 1;" ::: "memory");
            __syncthreads();
            if (kc + 2 < NCHUNK) issue(kc + 2);
            else asm volatile("cp.async.commit_group;" ::: "memory");

            const uint32_t Ab = sb + A_ST(kc % 3);
            const uint32_t Bb = sb + B_ST(kc % 3);
            #pragma unroll
            for (int stp = 0; stp < 8; stp++) {
                const int hb = (stp >= 4) ? 128 : 0;
                const int g2 = stp & 3;
                uint32_t ar[4][4], br[2][4];
                #pragma unroll
                for (int mt = 0; mt < 4; mt++) {
                    const int row = wm * 64 + mt * 16 + (lane & 7) + ((lane >> 3) & 1) * 8 + hb;
                    const int grp = 2 * g2 + (lane >> 4);
                    ldsm4(ar[mt], Ab + row * 128 + ((grp ^ (row & 7)) << 4));
                }
                #pragma unroll
                for (int bt = 0; bt < 2; bt++) {
                    const int row = wn * 32 + bt * 16 + (lane & 7) + (lane >> 4) * 8 + hb;
                    const int grp = 2 * g2 + ((lane >> 3) & 1);
                    ldsm4(br[bt], Bb + row * 128 + ((grp ^ (row & 7)) << 4));
                }
                #pragma unroll
                for (int mt = 0; mt < 4; mt++)
                    #pragma unroll
                    for (int nt = 0; nt < 4; nt++)
                        mma16816(acc[mt][nt], ar[mt],
                                 br[nt >> 1][(nt & 1) * 2], br[nt >> 1][(nt & 1) * 2 + 1]);
            }
        }
    };

    issue(0); issue(1);

    run3(0, y0);                    // t=1: y0 = m1
    #pragma unroll
    for (int a = 0; a < 4; a++)
        #pragma unroll
        for (int b = 0; b < 4; b++)
            #pragma unroll
            for (int c = 0; c < 4; c++) y1[a][b][c] = y0[a][b][c];   // y1 = m1
    run3(1, y0);                    // t=2: y0 = m1 + m2
    #pragma unroll
    for (int a = 0; a < 4; a++)
        #pragma unroll
        for (int b = 0; b < 4; b++)
            #pragma unroll
            for (int c = 0; c < 4; c++)
                y1[a][b][c] = 2.0f * y1[a][b][c] - y0[a][b][c];      // y1 = m1 - m2
    run3(2, y0);                    // t=0: y0 = m0 + m1 + m2
    run3(3, y1);                    // t=3 (negated U): y1 = m1 - m2 - m3

    asm volatile("cp.async.wait_group 0;" ::: "memory");
    __syncthreads();

    // ---- epilogue: two 64-channel passes through smem float2 buffer ----
    float2* eb2 = (float2*)smem;
    #pragma unroll
    for (int pass = 0; pass < 2; pass++) {
        if ((wn >> 1) == pass) {
            const int rr = lane >> 2, cc = (lane & 3) * 2;
            #pragma unroll
            for (int mt = 0; mt < 4; mt++)
                #pragma unroll
                for (int nt = 0; nt < 4; nt++) {
                    const int m = wm * 64 + mt * 16 + rr;
                    const int n = (wn & 1) * 32 + nt * 8 + cc;
                    eb2[n * 130 + m]           = make_float2(y0[mt][nt][0], y1[mt][nt][0]);
                    eb2[(n + 1) * 130 + m]     = make_float2(y0[mt][nt][1], y1[mt][nt][1]);
                    eb2[n * 130 + m + 8]       = make_float2(y0[mt][nt][2], y1[mt][nt][2]);
                    eb2[(n + 1) * 130 + m + 8] = make_float2(y0[mt][nt][3], y1[mt][nt][3]);
                }
        }
        __syncthreads();
        for (int j = tid; j < 64 * 128; j += 256) {
            const int k = j >> 7;
            const int m = j & 127;
            const unsigned pp = p0 + m;
            const unsigned ni = pp / P2IMG;
            const unsigned rr = pp - ni * P2IMG;
            const unsigned hh = rr / W2;
            const unsigned w2 = rr - hh * W2;
            *(float2*)(out + ((size_t)(ni * KOUT + n0 + pass * 64 + k) * H_IN + hh)
                       * W_IN + 2 * w2) = eb2[k * 130 + m];
        }
        __syncthreads();
    }
}

extern "C" void kernel_launch(void* const* d_in, const int* in_sizes, int n_in,
                              void* d_out, int out_size) {
    const float* x = (const float*)d_in[0];
    const float* w = (const float*)d_in[1];
    float* out = (float*)d_out;

    cudaFuncSetAttribute(conv_wino, cudaFuncAttributeMaxDynamicSharedMemorySize,
                         SMEM_TOTAL);

    dim3 gx(H_IN, NIMG);
    prep_xw<<<gx, 256>>>(x);
    prep_wu<<<(4 * 3 * KOUT * C_IN + 255) / 256, 256>>>(w);
    dim3 grid(P2TOT / 128, KOUT / 128);
    conv_wino<<<grid, 256, SMEM_TOTAL>>>(out);
}

// round 11
// speedup vs baseline: 1.4507x; 1.3627x over previous
#include <cuda_runtime.h>
#include <cuda_fp16.h>
#include <cstdint>

#define H_IN 56
#define W_IN 56
#define C_IN 128
#define KOUT 256
#define NIMG 32
#define W2   28                      // output-pair columns
#define P2TOT (NIMG*H_IN*W2)         // 50176 GEMM rows
#define P2IMG (H_IN*W2)              // 1568
#define VSTRIDE ((size_t)P2TOT*C_IN) // per-t V plane
#define NCHUNK 24                    // 4 GEMMs x 3 r x 2 c-halves, K=64 each

// Winograd-transformed scratch
__device__ __align__(128) __half g_v[4 * VSTRIDE];            // [t][p2][c]
__device__ __align__(128) __half g_u[4 * 3 * KOUT * C_IN];    // [t][r][k][c]

__constant__ int c_ord[4] = {1, 2, 0, 3};   // GEMM processing order -> t

__device__ __forceinline__ float quant16f(float v) {
    float r = rintf(v * 4096.0f);
    r = fminf(fmaxf(r, -32768.0f), 32767.0f);
    return r * (1.0f / 4096.0f);
}

__device__ __forceinline__ uint32_t su32(const void* p) {
    uint32_t a;
    asm("{ .reg .u64 t; cvta.to.shared.u64 t, %1; cvt.u32.u64 %0, t; }"
        : "=r"(a) : "l"(p));
    return a;
}

// ---------------- merged pre-kernel ----------------
// blocks [0, 1792): V transform, block b -> (h = b%56, n = b/56)
// blocks [1792, 1792+1536): U transform, 256 elems each
#define NBLK_X 1792
#define NBLK_W 1536

__global__ void prep_all(const float* __restrict__ x, const float* __restrict__ w) {
    const int b = blockIdx.x;
    const int tid = threadIdx.x;

    if (b >= NBLK_X) {
        // ---- U transform: [t][r][k][c]; t=3 negated ----
        int idx = (b - NBLK_X) * 256 + tid;
        int t = idx / (3 * KOUT * C_IN);
        int r = (idx / (KOUT * C_IN)) % 3;
        int k = (idx >> 7) & 255;
        int c = idx & 127;
        const float* gp = w + (size_t)k * 1152 + c * 9 + r * 3;
        float g0 = quant16f(gp[0]), g1 = quant16f(gp[1]), g2 = quant16f(gp[2]);
        float u;
        if (t == 0) u = g0;
        else if (t == 1) u = 0.5f * (g0 + g1 + g2);
        else if (t == 2) u = 0.5f * (g0 - g1 + g2);
        else u = -g2;
        g_u[((size_t)((t * 3 + r) * KOUT + k)) * C_IN + c] = __float2half(u);
        return;
    }

    // ---- V transform: one (n,h) row, all 128 c ----
    __shared__ __half xs[C_IN][58];   // [c][w+1], w=-1..56
    const int h = b % 56;
    const int n = b / 56;

    for (int i = tid; i < C_IN * W_IN; i += 256) {
        int c = i / W_IN, ww = i - c * W_IN;
        xs[c][ww + 1] = __float2half(
            quant16f(x[(((size_t)n * C_IN + c) * H_IN + h) * W_IN + ww]));
    }
    if (tid < C_IN) { xs[tid][0] = __float2half(0.f); xs[tid][57] = __float2half(0.f); }
    __syncthreads();

    const size_t pbase = ((size_t)(n * H_IN + h) * W2) * C_IN;
    for (int j = tid; j < W2 * (C_IN / 2); j += 256) {
        int cp = (j & 63) * 2, w2 = j >> 6;
        float d0a = __half2float(xs[cp][2 * w2]);
        float d1a = __half2float(xs[cp][2 * w2 + 1]);
        float d2a = __half2float(xs[cp][2 * w2 + 2]);
        float d3a = __half2float(xs[cp][2 * w2 + 3]);
        float d0b = __half2float(xs[cp + 1][2 * w2]);
        float d1b = __half2float(xs[cp + 1][2 * w2 + 1]);
        float d2b = __half2float(xs[cp + 1][2 * w2 + 2]);
        float d3b = __half2float(xs[cp + 1][2 * w2 + 3]);
        size_t o = pbase + (size_t)w2 * C_IN + cp;
        *(__half2*)&g_v[o]               = __floats2half2_rn(d0a - d2a, d0b - d2b);
        *(__half2*)&g_v[VSTRIDE + o]     = __floats2half2_rn(d1a + d2a, d1b + d2b);
        *(__half2*)&g_v[2 * VSTRIDE + o] = __floats2half2_rn(d2a - d1a, d2b - d1b);
        *(__half2*)&g_v[3 * VSTRIDE + o] = __floats2half2_rn(d1a - d3a, d1b - d3b);
    }
}

// ---------------- main kernel (R8 engine, single sync per chunk) ----------------
// smem: 4 stages x (A 16KB [128 p2 x 128B] + B 16KB [128 k x 128B])
#define A_ST(s) ((s) * 16384u)
#define B_ST(s) (65536u + (s) * 16384u)
#define SMEM_TOTAL 131072

__device__ __forceinline__ void cp16(uint32_t dst, const void* src, uint32_t ssz) {
    asm volatile("cp.async.cg.shared.global [%0], [%1], 16, %2;"
                 :: "r"(dst), "l"(src), "r"(ssz) : "memory");
}

__device__ __forceinline__ void ldsm4(uint32_t* r, uint32_t addr) {
    asm volatile("ldmatrix.sync.aligned.m8n8.x4.shared.b16 {%0,%1,%2,%3}, [%4];"
                 : "=r"(r[0]), "=r"(r[1]), "=r"(r[2]), "=r"(r[3]) : "r"(addr));
}

__device__ __forceinline__ void mma16816(float* c, const uint32_t* a,
                                         uint32_t b0, uint32_t b1) {
    asm volatile(
        "mma.sync.aligned.m16n8k16.row.col.f32.f16.f16.f32 "
        "{%0,%1,%2,%3}, {%4,%5,%6,%7}, {%8,%9}, {%0,%1,%2,%3};"
        : "+f"(c[0]), "+f"(c[1]), "+f"(c[2]), "+f"(c[3])
        : "r"(a[0]), "r"(a[1]), "r"(a[2]), "r"(a[3]), "r"(b0), "r"(b1));
}

__global__ __launch_bounds__(256, 1) void conv_wino(float* __restrict__ out) {
    extern __shared__ char smem[];
    const uint32_t sb = su32(smem);
    const int tid = threadIdx.x;
    const int wid = tid >> 5, lane = tid & 31;
    const int wm = wid & 1, wn = wid >> 1;       // warp tile: 64m x 32n
    const unsigned p0 = blockIdx.x << 7;
    const int n0 = blockIdx.y << 7;

    // staging coords: row = tid>>1 (128 rows x 128B), 64B half = tid&1
    const int rowT = tid >> 1, half = tid & 1;
    const unsigned p2 = p0 + rowT;
    const unsigned nImg = p2 / P2IMG;
    const unsigned rem = p2 - nImg * P2IMG;
    const int ho = (int)(rem / W2);

    auto issue = [&](int kc) {
        const int st = kc & 3;
        const int gg = kc / 6;
        const int sub = kc - 6 * gg;
        const int r = sub >> 1;
        const int ch0 = (sub & 1) << 6;
        const int tsel = c_ord[gg];
        // A: V_t at input row hi = ho + r - 1 (zero-fill OOB)
        const int hi = ho + r - 1;
        const bool valid = (unsigned)hi < H_IN;
        const size_t arow = valid ? (size_t)p2 + (size_t)(r - 1) * W2 : (size_t)p2;
        const uint32_t ssz = valid ? 16u : 0u;
        const __half* asrc = g_v + (size_t)tsel * VSTRIDE + arow * C_IN
                             + ch0 + half * 32;
        // B: U_t[r][n0+rowT][ch0..]
        const __half* bsrc = g_u + ((size_t)((tsel * 3 + r) * KOUT + n0 + rowT)) * C_IN
                             + ch0 + half * 32;
        #pragma unroll
        for (int j = 0; j < 4; j++) {
            const uint32_t g = half * 4 + j;
            const uint32_t sw = (g ^ (rowT & 7)) << 4;
            cp16(sb + A_ST(st) + rowT * 128 + sw, asrc + j * 8, ssz);
            cp16(sb + B_ST(st) + rowT * 128 + sw, bsrc + j * 8, 16u);
        }
        asm volatile("cp.async.commit_group;" ::: "memory");
    };

    float y0[4][4][4], y1[4][4][4];
    #pragma unroll
    for (int a = 0; a < 4; a++)
        #pragma unroll
        for (int b = 0; b < 4; b++)
            #pragma unroll
            for (int c = 0; c < 4; c++) { y0[a][b][c] = 0.f; y1[a][b][c] = 0.f; }

    auto run6 = [&](int gbase, float (&acc)[4][4][4]) {
        for (int sub = 0; sub < 6; sub++) {
            const int kc = gbase * 6 + sub;
            asm volatile("cp.async.wait_group 2;" ::: "memory");
            __syncthreads();
            if (kc + 3 < NCHUNK) issue(kc + 3);
            else asm volatile("cp.async.commit_group;" ::: "memory");

            const uint32_t Ab = sb + A_ST(kc & 3);
            const uint32_t Bb = sb + B_ST(kc & 3);
            #pragma unroll
            for (int stp = 0; stp < 4; stp++) {
                uint32_t ar[4][4], br[2][4];
                #pragma unroll
                for (int mt = 0; mt < 4; mt++) {
                    const int row = wm * 64 + mt * 16 + (lane & 7) + ((lane >> 3) & 1) * 8;
                    const int grp = 2 * stp + (lane >> 4);
                    ldsm4(ar[mt], Ab + row * 128 + ((grp ^ (row & 7)) << 4));
                }
                #pragma unroll
                for (int bt = 0; bt < 2; bt++) {
                    const int row = wn * 32 + bt * 16 + (lane & 7) + (lane >> 4) * 8;
                    const int grp = 2 * stp + ((lane >> 3) & 1);
                    ldsm4(br[bt], Bb + row * 128 + ((grp ^ (row & 7)) << 4));
                }
                #pragma unroll
                for (int mt = 0; mt < 4; mt++)
                    #pragma unroll
                    for (int nt = 0; nt < 4; nt++)
                        mma16816(acc[mt][nt], ar[mt],
                                 br[nt >> 1][(nt & 1) * 2], br[nt >> 1][(nt & 1) * 2 + 1]);
            }
            // single sync per chunk: next iteration's top sync covers the
            // stage-reuse hazard (see theory); trailing sync removed.
        }
    };

    issue(0); issue(1); issue(2);

    run6(0, y0);                    // t=1: y0 = m1
    #pragma unroll
    for (int a = 0; a < 4; a++)
        #pragma unroll
        for (int b = 0; b < 4; b++)
            #pragma unroll
            for (int c = 0; c < 4; c++) y1[a][b][c] = y0[a][b][c];   // y1 = m1
    run6(1, y0);                    // t=2: y0 = m1 + m2
    #pragma unroll
    for (int a = 0; a < 4; a++)
        #pragma unroll
        for (int b = 0; b < 4; b++)
            #pragma unroll
            for (int c = 0; c < 4; c++)
                y1[a][b][c] = 2.0f * y1[a][b][c] - y0[a][b][c];      // y1 = m1 - m2
    run6(2, y0);                    // t=0: y0 = m0 + m1 + m2
    run6(3, y1);                    // t=3 (negated U): y1 = m1 - m2 - m3

    asm volatile("cp.async.wait_group 0;" ::: "memory");
    __syncthreads();

    // ---- epilogue: two 64-channel passes through smem float2 buffer ----
    float2* eb2 = (float2*)smem;
    #pragma unroll
    for (int pass = 0; pass < 2; pass++) {
        if ((wn >> 1) == pass) {
            const int rr = lane >> 2, cc = (lane & 3) * 2;
            #pragma unroll
            for (int mt = 0; mt < 4; mt++)
                #pragma unroll
                for (int nt = 0; nt < 4; nt++) {
                    const int m = wm * 64 + mt * 16 + rr;
                    const int n = (wn & 1) * 32 + nt * 8 + cc;
                    eb2[n * 130 + m]           = make_float2(y0[mt][nt][0], y1[mt][nt][0]);
                    eb2[(n + 1) * 130 + m]     = make_float2(y0[mt][nt][1], y1[mt][nt][1]);
                    eb2[n * 130 + m + 8]       = make_float2(y0[mt][nt][2], y1[mt][nt][2]);
                    eb2[(n + 1) * 130 + m + 8] = make_float2(y0[mt][nt][3], y1[mt][nt][3]);
                }
        }
        __syncthreads();
        for (int j = tid; j < 64 * 128; j += 256) {
            const int k = j >> 7;
            const int m = j & 127;
            const unsigned pp = p0 + m;
            const unsigned ni = pp / P2IMG;
            const unsigned rr = pp - ni * P2IMG;
            const unsigned hh = rr / W2;
            const unsigned w2 = rr - hh * W2;
            *(float2*)(out + ((size_t)(ni * KOUT + n0 + pass * 64 + k) * H_IN + hh)
                       * W_IN + 2 * w2) = eb2[k * 130 + m];
        }
        __syncthreads();
    }
}

extern "C" void kernel_launch(void* const* d_in, const int* in_sizes, int n_in,
                              void* d_out, int out_size) {
    const float* x = (const float*)d_in[0];
    const float* w = (const float*)d_in[1];
    float* out = (float*)d_out;

    cudaFuncSetAttribute(conv_wino, cudaFuncAttributeMaxDynamicSharedMemorySize,
                         SMEM_TOTAL);

    prep_all<<<NBLK_X + NBLK_W, 256>>>(x, w);
    dim3 grid(P2TOT / 128, KOUT / 128);
    conv_wino<<<grid, 256, SMEM_TOTAL>>>(out);
}

// round 12
// speedup vs baseline: 1.5897x; 1.0958x over previous
#include <cuda_runtime.h>
#include <cuda_fp16.h>
#include <cstdint>

#define H_IN 56
#define W_IN 56
#define C_IN 128
#define KOUT 256
#define NIMG 32
#define W2   28                      // output-pair columns
#define P2TOT (NIMG*H_IN*W2)         // 50176 GEMM rows
#define P2IMG (H_IN*W2)              // 1568
#define VSTRIDE ((size_t)P2TOT*C_IN) // per-t V plane
#define NCHUNK 24                    // 4 GEMMs x 3 r x 2 c-halves, K=64 each

// Winograd-transformed scratch
__device__ __align__(128) __half g_v[4 * VSTRIDE];            // [t][p2][c]
__device__ __align__(128) __half g_u[4 * 3 * KOUT * C_IN];    // [t][r][k][c]

__constant__ int c_ord[4] = {1, 2, 0, 3};   // GEMM processing order -> t

__device__ __forceinline__ float quant16f(float v) {
    float r = rintf(v * 4096.0f);
    r = fminf(fmaxf(r, -32768.0f), 32767.0f);
    return r * (1.0f / 4096.0f);
}

__device__ __forceinline__ uint32_t su32(const void* p) {
    uint32_t a;
    asm("{ .reg .u64 t; cvta.to.shared.u64 t, %1; cvt.u32.u64 %0, t; }"
        : "=r"(a) : "l"(p));
    return a;
}

// ---------------- merged pre-kernel ----------------
#define NBLK_X 1792
#define NBLK_W 1536

__global__ void prep_all(const float* __restrict__ x, const float* __restrict__ w) {
    const int b = blockIdx.x;
    const int tid = threadIdx.x;

    if (b >= NBLK_X) {
        // ---- U transform: [t][r][k][c]; t=3 negated ----
        int idx = (b - NBLK_X) * 256 + tid;
        int t = idx / (3 * KOUT * C_IN);
        int r = (idx / (KOUT * C_IN)) % 3;
        int k = (idx >> 7) & 255;
        int c = idx & 127;
        const float* gp = w + (size_t)k * 1152 + c * 9 + r * 3;
        float g0 = quant16f(gp[0]), g1 = quant16f(gp[1]), g2 = quant16f(gp[2]);
        float u;
        if (t == 0) u = g0;
        else if (t == 1) u = 0.5f * (g0 + g1 + g2);
        else if (t == 2) u = 0.5f * (g0 - g1 + g2);
        else u = -g2;
        g_u[((size_t)((t * 3 + r) * KOUT + k)) * C_IN + c] = __float2half(u);
        return;
    }

    // ---- V transform: one (n,h) row, all 128 c ----
    __shared__ __half xs[C_IN][58];   // [c][w+1], w=-1..56
    const int h = b % 56;
    const int n = b / 56;

    for (int i = tid; i < C_IN * W_IN; i += 256) {
        int c = i / W_IN, ww = i - c * W_IN;
        xs[c][ww + 1] = __float2half(
            quant16f(x[(((size_t)n * C_IN + c) * H_IN + h) * W_IN + ww]));
    }
    if (tid < C_IN) { xs[tid][0] = __float2half(0.f); xs[tid][57] = __float2half(0.f); }
    __syncthreads();

    const size_t pbase = ((size_t)(n * H_IN + h) * W2) * C_IN;
    for (int j = tid; j < W2 * (C_IN / 2); j += 256) {
        int cp = (j & 63) * 2, w2 = j >> 6;
        float d0a = __half2float(xs[cp][2 * w2]);
        float d1a = __half2float(xs[cp][2 * w2 + 1]);
        float d2a = __half2float(xs[cp][2 * w2 + 2]);
        float d3a = __half2float(xs[cp][2 * w2 + 3]);
        float d0b = __half2float(xs[cp + 1][2 * w2]);
        float d1b = __half2float(xs[cp + 1][2 * w2 + 1]);
        float d2b = __half2float(xs[cp + 1][2 * w2 + 2]);
        float d3b = __half2float(xs[cp + 1][2 * w2 + 3]);
        size_t o = pbase + (size_t)w2 * C_IN + cp;
        *(__half2*)&g_v[o]               = __floats2half2_rn(d0a - d2a, d0b - d2b);
        *(__half2*)&g_v[VSTRIDE + o]     = __floats2half2_rn(d1a + d2a, d1b + d2b);
        *(__half2*)&g_v[2 * VSTRIDE + o] = __floats2half2_rn(d2a - d1a, d2b - d1b);
        *(__half2*)&g_v[3 * VSTRIDE + o] = __floats2half2_rn(d1a - d3a, d1b - d3b);
    }
}

// ---------------- main kernel: 64Mx128N CTA, 8 warps(32x32), 2 CTAs/SM ----------------
// smem: 4 stages x (A 8KB [64 p2 x 128B] + B 16KB [128 k x 128B]) = 96KB
#define A_ST(s) ((s) * 24576u)
#define B_ST(s) ((s) * 24576u + 8192u)
#define SMEM_TOTAL 98304

__device__ __forceinline__ void cp16(uint32_t dst, const void* src, uint32_t ssz) {
    asm volatile("cp.async.cg.shared.global [%0], [%1], 16, %2;"
                 :: "r"(dst), "l"(src), "r"(ssz) : "memory");
}

__device__ __forceinline__ void ldsm4(uint32_t* r, uint32_t addr) {
    asm volatile("ldmatrix.sync.aligned.m8n8.x4.shared.b16 {%0,%1,%2,%3}, [%4];"
                 : "=r"(r[0]), "=r"(r[1]), "=r"(r[2]), "=r"(r[3]) : "r"(addr));
}

__device__ __forceinline__ void mma16816(float* c, const uint32_t* a,
                                         uint32_t b0, uint32_t b1) {
    asm volatile(
        "mma.sync.aligned.m16n8k16.row.col.f32.f16.f16.f32 "
        "{%0,%1,%2,%3}, {%4,%5,%6,%7}, {%8,%9}, {%0,%1,%2,%3};"
        : "+f"(c[0]), "+f"(c[1]), "+f"(c[2]), "+f"(c[3])
        : "r"(a[0]), "r"(a[1]), "r"(a[2]), "r"(a[3]), "r"(b0), "r"(b1));
}

__global__ __launch_bounds__(256, 2) void conv_wino(float* __restrict__ out) {
    extern __shared__ char smem[];
    const uint32_t sb = su32(smem);
    const int tid = threadIdx.x;
    const int wid = tid >> 5, lane = tid & 31;
    const int wm = wid & 1, wn = wid >> 1;       // warp tile: 32m x 32n
    const unsigned p0 = blockIdx.x << 6;
    const int n0 = blockIdx.y << 7;

    // A staging: row = tid>>2 (64 rows x 128B), 32B quarter = tid&3 (2 cp16)
    const int rowA = tid >> 2, qA = tid & 3;
    const unsigned p2 = p0 + rowA;
    const unsigned nImg = p2 / P2IMG;
    const unsigned rem = p2 - nImg * P2IMG;
    const int ho = (int)(rem / W2);
    // B staging: row = tid>>1 (128 rows x 128B), 64B half = tid&1 (4 cp16)
    const int rowB = tid >> 1, halfB = tid & 1;

    auto issue = [&](int kc) {
        const int st = kc & 3;
        const int gg = kc / 6;
        const int sub = kc - 6 * gg;
        const int r = sub >> 1;
        const int ch0 = (sub & 1) << 6;
        const int tsel = c_ord[gg];
        // A: V_t at input row hi = ho + r - 1 (zero-fill OOB)
        const int hi = ho + r - 1;
        const bool valid = (unsigned)hi < H_IN;
        const size_t arow = valid ? (size_t)p2 + (size_t)(r - 1) * W2 : (size_t)p2;
        const uint32_t ssz = valid ? 16u : 0u;
        const __half* asrc = g_v + (size_t)tsel * VSTRIDE + arow * C_IN
                             + ch0 + qA * 16;
        #pragma unroll
        for (int j = 0; j < 2; j++) {
            const uint32_t g = qA * 2 + j;
            const uint32_t sw = (g ^ (rowA & 7)) << 4;
            cp16(sb + A_ST(st) + rowA * 128 + sw, asrc + j * 8, ssz);
        }
        // B: U_t[r][n0+rowB][ch0..]
        const __half* bsrc = g_u + ((size_t)((tsel * 3 + r) * KOUT + n0 + rowB)) * C_IN
                             + ch0 + halfB * 32;
        #pragma unroll
        for (int j = 0; j < 4; j++) {
            const uint32_t g = halfB * 4 + j;
            const uint32_t sw = (g ^ (rowB & 7)) << 4;
            cp16(sb + B_ST(st) + rowB * 128 + sw, bsrc + j * 8, 16u);
        }
        asm volatile("cp.async.commit_group;" ::: "memory");
    };

    float y0[2][4][4], y1[2][4][4];
    #pragma unroll
    for (int a = 0; a < 2; a++)
        #pragma unroll
        for (int b = 0; b < 4; b++)
            #pragma unroll
            for (int c = 0; c < 4; c++) { y0[a][b][c] = 0.f; y1[a][b][c] = 0.f; }

    auto run6 = [&](int gbase, float (&acc)[2][4][4]) {
        for (int sub = 0; sub < 6; sub++) {
            const int kc = gbase * 6 + sub;
            asm volatile("cp.async.wait_group 2;" ::: "memory");
            __syncthreads();
            if (kc + 3 < NCHUNK) issue(kc + 3);
            else asm volatile("cp.async.commit_group;" ::: "memory");

            const uint32_t Ab = sb + A_ST(kc & 3);
            const uint32_t Bb = sb + B_ST(kc & 3);
            #pragma unroll
            for (int stp = 0; stp < 4; stp++) {
                uint32_t ar[2][4], br[2][4];
                #pragma unroll
                for (int mt = 0; mt < 2; mt++) {
                    const int row = wm * 32 + mt * 16 + (lane & 7) + ((lane >> 3) & 1) * 8;
                    const int grp = 2 * stp + (lane >> 4);
                    ldsm4(ar[mt], Ab + row * 128 + ((grp ^ (row & 7)) << 4));
                }
                #pragma unroll
                for (int bt = 0; bt < 2; bt++) {
                    const int row = wn * 32 + bt * 16 + (lane & 7) + (lane >> 4) * 8;
                    const int grp = 2 * stp + ((lane >> 3) & 1);
                    ldsm4(br[bt], Bb + row * 128 + ((grp ^ (row & 7)) << 4));
                }
                #pragma unroll
                for (int mt = 0; mt < 2; mt++)
                    #pragma unroll
                    for (int nt = 0; nt < 4; nt++)
                        mma16816(acc[mt][nt], ar[mt],
                                 br[nt >> 1][(nt & 1) * 2], br[nt >> 1][(nt & 1) * 2 + 1]);
            }
        }
    };

    issue(0); issue(1); issue(2);

    run6(0, y0);                    // t=1: y0 = m1
    #pragma unroll
    for (int a = 0; a < 2; a++)
        #pragma unroll
        for (int b = 0; b < 4; b++)
            #pragma unroll
            for (int c = 0; c < 4; c++) y1[a][b][c] = y0[a][b][c];   // y1 = m1
    run6(1, y0);                    // t=2: y0 = m1 + m2
    #pragma unroll
    for (int a = 0; a < 2; a++)
        #pragma unroll
        for (int b = 0; b < 4; b++)
            #pragma unroll
            for (int c = 0; c < 4; c++)
                y1[a][b][c] = 2.0f * y1[a][b][c] - y0[a][b][c];      // y1 = m1 - m2
    run6(2, y0);                    // t=0: y0 = m0 + m1 + m2
    run6(3, y1);                    // t=3 (negated U): y1 = m1 - m2 - m3

    asm volatile("cp.async.wait_group 0;" ::: "memory");
    __syncthreads();

    // ---- epilogue: (y0,y1) -> smem float2 [128 n][66] -> coalesced pairs ----
    float2* eb2 = (float2*)smem;
    {
        const int rr = lane >> 2, cc = (lane & 3) * 2;
        #pragma unroll
        for (int mt = 0; mt < 2; mt++)
            #pragma unroll
            for (int nt = 0; nt < 4; nt++) {
                const int m = wm * 32 + mt * 16 + rr;
                const int n = wn * 32 + nt * 8 + cc;
                eb2[n * 66 + m]           = make_float2(y0[mt][nt][0], y1[mt][nt][0]);
                eb2[(n + 1) * 66 + m]     = make_float2(y0[mt][nt][1], y1[mt][nt][1]);
                eb2[n * 66 + m + 8]       = make_float2(y0[mt][nt][2], y1[mt][nt][2]);
                eb2[(n + 1) * 66 + m + 8] = make_float2(y0[mt][nt][3], y1[mt][nt][3]);
            }
    }
    __syncthreads();
    for (int j = tid; j < 128 * 64; j += 256) {
        const int k = j >> 6;            // output channel 0..127
        const int m = j & 63;            // pixel-pair in tile
        const unsigned pp = p0 + m;
        const unsigned ni = pp / P2IMG;
        const unsigned rr = pp - ni * P2IMG;
        const unsigned hh = rr / W2;
        const unsigned w2 = rr - hh * W2;
        *(float2*)(out + ((size_t)(ni * KOUT + n0 + k) * H_IN + hh) * W_IN + 2 * w2)
            = eb2[k * 66 + m];
    }
}

extern "C" void kernel_launch(void* const* d_in, const int* in_sizes, int n_in,
                              void* d_out, int out_size) {
    const float* x = (const float*)d_in[0];
    const float* w = (const float*)d_in[1];
    float* out = (float*)d_out;

    cudaFuncSetAttribute(conv_wino, cudaFuncAttributeMaxDynamicSharedMemorySize,
                         SMEM_TOTAL);

    prep_all<<<NBLK_X + NBLK_W, 256>>>(x, w);
    dim3 grid(P2TOT / 64, KOUT / 128);
    conv_wino<<<grid, 256, SMEM_TOTAL>>>(out);
}